// round 7
// baseline (speedup 1.0000x reference)
#include <cuda_runtime.h>
#include <cuda_bf16.h>
#include <math.h>

// Problem constants
#define T_STEPS 512
#define BATCH   128
#define HDIM    512
#define HDIM3   1536

typedef unsigned long long u64;

// ---------------------------------------------------------------------------
// Packed f32x2 helpers
// ---------------------------------------------------------------------------
__device__ __forceinline__ u64 pk2_(float lo, float hi) {
    u64 r;
    asm("mov.b64 %0, {%1, %2};"
        : "=l"(r) : "r"(__float_as_uint(lo)), "r"(__float_as_uint(hi)));
    return r;
}
__device__ __forceinline__ void upk2_(u64 v, float& lo, float& hi) {
    unsigned int a, b_;
    asm("mov.b64 {%0, %1}, %2;" : "=r"(a), "=r"(b_) : "l"(v));
    lo = __uint_as_float(a);
    hi = __uint_as_float(b_);
}
__device__ __forceinline__ u64 ffma2_(u64 a, u64 b, u64 c) {
    u64 d;
    asm("fma.rn.f32x2 %0, %1, %2, %3;" : "=l"(d) : "l"(a), "l"(b), "l"(c));
    return d;
}
__device__ __forceinline__ u64 fadd2_(u64 a, u64 b) {
    u64 d;
    asm("add.rn.f32x2 %0, %1, %2;" : "=l"(d) : "l"(a), "l"(b));
    return d;
}

// tf32 round-to-nearest conversion (bits kept in a b32 register)
__device__ __forceinline__ unsigned int tf32_(float x) {
    unsigned int r;
    asm("cvt.rna.tf32.f32 %0, %1;" : "=r"(r) : "f"(x));
    return r;
}

// ---------------------------------------------------------------------------
// Scratch: gi [T,B,3H]; h ping-pong stored TRANSPOSED: h[k*128+b]; barrier.
// ---------------------------------------------------------------------------
__device__ __align__(16) float g_gi[(size_t)T_STEPS * BATCH * HDIM3];
__device__ __align__(16) float g_h[2][BATCH * HDIM];
__device__ unsigned int g_arrive = 0;
__device__ unsigned int g_release = 0;

// ---------------------------------------------------------------------------
// Grid-wide sense-reversing barrier (all 128 blocks co-resident).
// Self-resetting; safe across graph replays (generation read fresh each time).
// ---------------------------------------------------------------------------
#define SCAN_BLOCKS 128

__device__ __forceinline__ void grid_barrier(int nblk) {
    __syncthreads();
    if (threadIdx.x == 0) {
        __threadfence();
        unsigned gen = atomicAdd(&g_release, 0u);
        unsigned ticket = atomicAdd(&g_arrive, 1u);
        if (ticket == (unsigned)(nblk - 1)) {
            atomicExch(&g_arrive, 0u);
            __threadfence();
            atomicAdd(&g_release, 1u);
        } else {
            while (*((volatile unsigned int*)&g_release) == gen) {
                __nanosleep(16);
            }
        }
        __threadfence();
    }
    __syncthreads();
}

// ---------------------------------------------------------------------------
// Pre-GEMM on TENSOR CORES: gi[m,n] = sum_k x[m,k]*Wi[k,n] + bi[n]
// M=65536, N=1536, K=512. tf32 mma.sync.m16n8k8 with 3xTF32 compensation:
// x = xh + xl, W = wh + wl (tf32 splits); acc += xh*wh + xh*wl + xl*wh.
// Block tile 128x128x16, 256 threads = 8 warps in 4(M) x 2(N); warp 32x64.
// SMEM stores {hi,lo} tf32 pairs adjacently -> LDS.64 feeds both terms.
// ---------------------------------------------------------------------------
#define GBM 128
#define GBN 128
#define GBK 16
#define ASTRIDE 130   // u64 stride, padded: bank = (4*k + 2*m) % 32 pattern
#define BSTRIDE 130

__device__ __forceinline__ void mma_tf32(
    float& d0, float& d1, float& d2, float& d3,
    unsigned int a0, unsigned int a1, unsigned int a2, unsigned int a3,
    unsigned int b0, unsigned int b1)
{
    asm volatile(
        "mma.sync.aligned.m16n8k8.row.col.f32.tf32.tf32.f32 "
        "{%0,%1,%2,%3}, {%4,%5,%6,%7}, {%8,%9}, {%0,%1,%2,%3};"
        : "+f"(d0), "+f"(d1), "+f"(d2), "+f"(d3)
        : "r"(a0), "r"(a1), "r"(a2), "r"(a3), "r"(b0), "r"(b1));
}

__global__ __launch_bounds__(256) void gemm_gi_tc_kernel(
    const float* __restrict__ X, const float* __restrict__ Wi,
    const float* __restrict__ bi, float* __restrict__ gi)
{
    // As2[k][m] = {hi,lo} of X[m0+m][k0+k];  Bs2[k][n] = {hi,lo} of Wi.
    __shared__ __align__(16) u64 As2[GBK * ASTRIDE];
    __shared__ __align__(16) u64 Bs2[GBK * BSTRIDE];

    const int m0 = blockIdx.y * GBM;
    const int n0 = blockIdx.x * GBN;
    const int tid = threadIdx.x;
    const int wid = tid >> 5;
    const int lane = tid & 31;
    const int g = lane >> 2;        // groupID
    const int tig = lane & 3;       // thread in group

    const int wm = (wid & 3) * 32;  // warp M offset in tile
    const int wn = (wid >> 2) * 64; // warp N offset in tile

    // Global load mapping
    const int xr = tid >> 1;              // 0..127 (row of X tile)
    const int xc = (tid & 1) * 8;         // col base 0 or 8
    const int wr = tid >> 4;              // 0..15 (row of Wi tile)
    const int wc = (tid & 15) * 8;        // col base

    float acc[2][8][4];
#pragma unroll
    for (int mf = 0; mf < 2; mf++)
#pragma unroll
        for (int nf = 0; nf < 8; nf++)
#pragma unroll
            for (int r = 0; r < 4; r++) acc[mf][nf][r] = 0.f;

    for (int k0 = 0; k0 < HDIM; k0 += GBK) {
        // Load + split X tile: 128 rows x 16 cols, transposed store As2[k][m]
#pragma unroll
        for (int h = 0; h < 2; h++) {
            float4 v = *(const float4*)&X[(size_t)(m0 + xr) * HDIM + k0 + xc + h * 4];
            float xs[4] = {v.x, v.y, v.z, v.w};
#pragma unroll
            for (int i = 0; i < 4; i++) {
                unsigned int hi = tf32_(xs[i]);
                unsigned int lo = tf32_(xs[i] - __uint_as_float(hi));
                As2[(xc + h * 4 + i) * ASTRIDE + xr] =
                    pk2_(__uint_as_float(hi), __uint_as_float(lo));
            }
        }
        // Load + split Wi tile: 16 rows x 128 cols, Bs2[k][n]
#pragma unroll
        for (int h = 0; h < 2; h++) {
            float4 v = *(const float4*)&Wi[(size_t)(k0 + wr) * HDIM3 + n0 + wc + h * 4];
            float ws[4] = {v.x, v.y, v.z, v.w};
#pragma unroll
            for (int i = 0; i < 4; i++) {
                unsigned int hi = tf32_(ws[i]);
                unsigned int lo = tf32_(ws[i] - __uint_as_float(hi));
                Bs2[wr * BSTRIDE + wc + h * 4 + i] =
                    pk2_(__uint_as_float(hi), __uint_as_float(lo));
            }
        }
        __syncthreads();

#pragma unroll
        for (int kf = 0; kf < 2; kf++) {
            const int kb = kf * 8;
            // A fragments for 2 m-frags: rows g, g+8; cols tig, tig+4
            unsigned int ah[2][4], al[2][4];
#pragma unroll
            for (int mf = 0; mf < 2; mf++) {
                int mrow = wm + mf * 16;
                float h0f, l0f, h1f, l1f, h2f, l2f, h3f, l3f;
                upk2_(As2[(kb + tig) * ASTRIDE + mrow + g], h0f, l0f);
                upk2_(As2[(kb + tig) * ASTRIDE + mrow + g + 8], h1f, l1f);
                upk2_(As2[(kb + tig + 4) * ASTRIDE + mrow + g], h2f, l2f);
                upk2_(As2[(kb + tig + 4) * ASTRIDE + mrow + g + 8], h3f, l3f);
                ah[mf][0] = __float_as_uint(h0f); al[mf][0] = __float_as_uint(l0f);
                ah[mf][1] = __float_as_uint(h1f); al[mf][1] = __float_as_uint(l1f);
                ah[mf][2] = __float_as_uint(h2f); al[mf][2] = __float_as_uint(l2f);
                ah[mf][3] = __float_as_uint(h3f); al[mf][3] = __float_as_uint(l3f);
            }
#pragma unroll
            for (int nf = 0; nf < 8; nf++) {
                int ncol = wn + nf * 8 + g;
                float bh0f, bl0f, bh1f, bl1f;
                upk2_(Bs2[(kb + tig) * BSTRIDE + ncol], bh0f, bl0f);
                upk2_(Bs2[(kb + tig + 4) * BSTRIDE + ncol], bh1f, bl1f);
                unsigned int bh0 = __float_as_uint(bh0f), bl0 = __float_as_uint(bl0f);
                unsigned int bh1 = __float_as_uint(bh1f), bl1 = __float_as_uint(bl1f);
#pragma unroll
                for (int mf = 0; mf < 2; mf++) {
                    mma_tf32(acc[mf][nf][0], acc[mf][nf][1], acc[mf][nf][2], acc[mf][nf][3],
                             ah[mf][0], ah[mf][1], ah[mf][2], ah[mf][3], bh0, bh1);
                    mma_tf32(acc[mf][nf][0], acc[mf][nf][1], acc[mf][nf][2], acc[mf][nf][3],
                             ah[mf][0], ah[mf][1], ah[mf][2], ah[mf][3], bl0, bl1);
                    mma_tf32(acc[mf][nf][0], acc[mf][nf][1], acc[mf][nf][2], acc[mf][nf][3],
                             al[mf][0], al[mf][1], al[mf][2], al[mf][3], bh0, bh1);
                }
            }
        }
        __syncthreads();
    }

    // Epilogue: C frag c0/c1 at (row g, col 2*tig/(+1)); c2/c3 at row g+8.
#pragma unroll
    for (int mf = 0; mf < 2; mf++) {
#pragma unroll
        for (int nf = 0; nf < 8; nf++) {
            int n = n0 + wn + nf * 8 + 2 * tig;
            float b0v = bi[n], b1v = bi[n + 1];
            int mA = m0 + wm + mf * 16 + g;
            int mB = mA + 8;
            float2 oA = make_float2(acc[mf][nf][0] + b0v, acc[mf][nf][1] + b1v);
            float2 oB = make_float2(acc[mf][nf][2] + b0v, acc[mf][nf][3] + b1v);
            *(float2*)&gi[(size_t)mA * HDIM3 + n] = oA;
            *(float2*)&gi[(size_t)mB * HDIM3 + n] = oB;
        }
    }
}

// ---------------------------------------------------------------------------
// Persistent scan (round-4 configuration, best measured): 128 blocks x 512
// threads, 4-way k-split, FFMA2 accumulators, one grid barrier per step.
// ---------------------------------------------------------------------------
#define SCAN_THREADS 512
#define KSPLIT 128
#define JCHUNK 4

__device__ __forceinline__ float fast_sigmoid(float x) {
    return 1.0f / (1.0f + __expf(-x));
}
__device__ __forceinline__ float fast_tanh(float x) {
    return 2.0f / (1.0f + __expf(-2.0f * x)) - 1.0f;
}

__global__ __launch_bounds__(SCAN_THREADS) void scan_kernel(
    const float* __restrict__ h0, const float* __restrict__ Wh,
    const float* __restrict__ bhn,
    float* __restrict__ out_h, float* __restrict__ out_ys)
{
    __shared__ __align__(16) float wh_s[HDIM * 12];
    __shared__ __align__(16) u64 red2[3][6 * BATCH];

    const int tid = threadIdx.x;
    const int b = tid & (BATCH - 1);
    const int quarter = tid >> 7;
    const int kbase = quarter * KSPLIT;
    const int j0 = blockIdx.x * JCHUNK;

    for (int idx = tid; idx < HDIM * 12; idx += SCAN_THREADS) {
        int kk = idx / 12;
        int c = idx - kk * 12;
        int col = (c >> 2) * HDIM + j0 + (c & 3);
        wh_s[idx] = Wh[(size_t)kk * HDIM3 + col];
    }

    float bn[JCHUNK];
#pragma unroll
    for (int c = 0; c < JCHUNK; c++) bn[c] = bhn[j0 + c];

    float hn[JCHUNK];
    {
        float4 v = *(const float4*)&h0[(size_t)b * HDIM + j0];
        hn[0] = v.x; hn[1] = v.y; hn[2] = v.z; hn[3] = v.w;
        if (quarter == 0) {
#pragma unroll
            for (int c = 0; c < JCHUNK; c++)
                g_h[0][(j0 + c) * BATCH + b] = hn[c];
        }
    }
    grid_barrier(SCAN_BLOCKS);

    for (int t = 0; t < T_STEPS; t++) {
        const float* __restrict__ hp = g_h[t & 1];
        float* __restrict__ hq = g_h[(t & 1) ^ 1];

        float4 gr, gz, gn;
        if (quarter == 0) {
            const float* gi = &g_gi[((size_t)t * BATCH + b) * HDIM3];
            gr = *(const float4*)&gi[j0];
            gz = *(const float4*)&gi[HDIM + j0];
            gn = *(const float4*)&gi[2 * HDIM + j0];
        }

        u64 acc2[6];
#pragma unroll
        for (int c = 0; c < 6; c++) acc2[c] = 0ull;

        float hv[8];
#pragma unroll
        for (int u = 0; u < 8; u++) hv[u] = hp[(kbase + u) * BATCH + b];

#pragma unroll 1
        for (int base = 0; base < KSPLIT; base += 8) {
            float hv_n[8];
            if (base + 8 < KSPLIT) {
#pragma unroll
                for (int u = 0; u < 8; u++)
                    hv_n[u] = hp[(kbase + base + 8 + u) * BATCH + b];
            }
#pragma unroll
            for (int u = 0; u < 8; u++) {
                const ulonglong2* w =
                    (const ulonglong2*)(wh_s + (kbase + base + u) * 12);
                ulonglong2 w01 = w[0], w23 = w[1], w45 = w[2];
                u64 h2 = pk2_(hv[u], hv[u]);
                acc2[0] = ffma2_(h2, w01.x, acc2[0]);
                acc2[1] = ffma2_(h2, w01.y, acc2[1]);
                acc2[2] = ffma2_(h2, w23.x, acc2[2]);
                acc2[3] = ffma2_(h2, w23.y, acc2[3]);
                acc2[4] = ffma2_(h2, w45.x, acc2[4]);
                acc2[5] = ffma2_(h2, w45.y, acc2[5]);
            }
#pragma unroll
            for (int u = 0; u < 8; u++) hv[u] = hv_n[u];
        }

        if (quarter > 0) {
#pragma unroll
            for (int c = 0; c < 6; c++) red2[quarter - 1][c * BATCH + b] = acc2[c];
        }
        __syncthreads();

        if (quarter == 0) {
#pragma unroll
            for (int c = 0; c < 6; c++) {
                acc2[c] = fadd2_(acc2[c], red2[0][c * BATCH + b]);
                acc2[c] = fadd2_(acc2[c], fadd2_(red2[1][c * BATCH + b],
                                                 red2[2][c * BATCH + b]));
            }
            float a[12];
#pragma unroll
            for (int c = 0; c < 6; c++) upk2_(acc2[c], a[2 * c], a[2 * c + 1]);

            float giR[4] = {gr.x, gr.y, gr.z, gr.w};
            float giZ[4] = {gz.x, gz.y, gz.z, gz.w};
            float giN[4] = {gn.x, gn.y, gn.z, gn.w};

#pragma unroll
            for (int c = 0; c < JCHUNK; c++) {
                float r = fast_sigmoid(giR[c] + a[c]);
                float z = fast_sigmoid(giZ[c] + a[4 + c]);
                float n = fast_tanh(giN[c] + r * (a[8 + c] + bn[c]));
                float hnew = (1.0f - z) * n + z * hn[c];
                hn[c] = hnew;
                hq[(j0 + c) * BATCH + b] = hnew;
            }

            *(float4*)&out_ys[((size_t)t * BATCH + b) * HDIM + j0] =
                make_float4(hn[0], hn[1], hn[2], hn[3]);
        }

        grid_barrier(SCAN_BLOCKS);
    }

    if (out_h && quarter == 0) {
        *(float4*)&out_h[(size_t)b * HDIM + j0] =
            make_float4(hn[0], hn[1], hn[2], hn[3]);
    }
}

// ---------------------------------------------------------------------------
// kernel_launch: inputs per metadata order: x, h0, Wi, bi, Wh, bhn
// ---------------------------------------------------------------------------
extern "C" void kernel_launch(void* const* d_in, const int* in_sizes, int n_in,
                              void* d_out, int out_size)
{
    const float* x   = (const float*)d_in[0];   // [T, B, H]
    const float* h0  = (const float*)d_in[1];   // [B, H]
    const float* Wi  = (const float*)d_in[2];   // [H, 3H]
    const float* bi  = (const float*)d_in[3];   // [3H]
    const float* Wh  = (const float*)d_in[4];   // [H, 3H]
    const float* bhn = (const float*)d_in[5];   // [H]

    float* out = (float*)d_out;
    float* out_h;
    float* out_ys;
    const long long ys_elems = (long long)T_STEPS * BATCH * HDIM;
    if ((long long)out_size >= ys_elems + (long long)BATCH * HDIM) {
        out_h = out;                    // (h_final, ys) flattened in order
        out_ys = out + (size_t)BATCH * HDIM;
    } else {
        out_h = nullptr;                // ys only
        out_ys = out;
    }

    float* gi;
    cudaGetSymbolAddress((void**)&gi, g_gi);

    // 1) gi = x @ Wi + bi  (tf32 tensor cores, 3xTF32 compensated)
    dim3 ggrid(HDIM3 / GBN, (T_STEPS * BATCH) / GBM);
    gemm_gi_tc_kernel<<<ggrid, 256>>>(x, Wi, bi, gi);

    // 2) persistent GRU scan
    scan_kernel<<<SCAN_BLOCKS, SCAN_THREADS>>>(h0, Wh, bhn, out_h, out_ys);
}

// round 8
// speedup vs baseline: 1.1827x; 1.1827x over previous
#include <cuda_runtime.h>
#include <cuda_bf16.h>
#include <math.h>

// Problem constants
#define T_STEPS 512
#define BATCH   128
#define HDIM    512
#define HDIM3   1536

typedef unsigned long long u64;
typedef unsigned int u32;

// ---------------------------------------------------------------------------
// bf16 helpers: pack two floats' bf16 into one u32 (f0 -> low 16, f1 -> high).
// split2: hi/lo bf16 decomposition of two floats, packed as k-pairs.
// ---------------------------------------------------------------------------
__device__ __forceinline__ u32 pkbf_(float f0, float f1) {
    unsigned short s0 = __bfloat16_as_ushort(__float2bfloat16_rn(f0));
    unsigned short s1 = __bfloat16_as_ushort(__float2bfloat16_rn(f1));
    return (u32)s0 | ((u32)s1 << 16);
}
__device__ __forceinline__ void split2_(float f0, float f1, u32& hi, u32& lo) {
    __nv_bfloat16 h0 = __float2bfloat16_rn(f0);
    __nv_bfloat16 h1 = __float2bfloat16_rn(f1);
    float r0 = f0 - __bfloat162float(h0);
    float r1 = f1 - __bfloat162float(h1);
    hi = (u32)__bfloat16_as_ushort(h0) | ((u32)__bfloat16_as_ushort(h1) << 16);
    lo = pkbf_(r0, r1);
}

// m16n8k16 bf16 MMA, fp32 accumulate (fragment layouts per PTX ISA).
__device__ __forceinline__ void mma_bf16(
    float& d0, float& d1, float& d2, float& d3,
    u32 a0, u32 a1, u32 a2, u32 a3, u32 b0, u32 b1)
{
    asm volatile(
        "mma.sync.aligned.m16n8k16.row.col.f32.bf16.bf16.f32 "
        "{%0,%1,%2,%3}, {%4,%5,%6,%7}, {%8,%9}, {%0,%1,%2,%3};"
        : "+f"(d0), "+f"(d1), "+f"(d2), "+f"(d3)
        : "r"(a0), "r"(a1), "r"(a2), "r"(a3), "r"(b0), "r"(b1));
}

// ---------------------------------------------------------------------------
// Scratch: gi [T,B,3H] fp32; h ping-pong as k-pair packed {hi,lo} bf16x2:
// g_h2[buf][kp*128 + b] = u64{ lo32 = bf16x2(h[2kp],h[2kp+1]) hi-part,
//                              hi32 = same for lo-part }.
// Barrier counters (sense-reversing, self-resetting).
// ---------------------------------------------------------------------------
#define KP_TOTAL 256   // 512 k / 2 per pair
__device__ __align__(16) float g_gi[(size_t)T_STEPS * BATCH * HDIM3];
__device__ __align__(16) u64 g_h2[2][KP_TOTAL * BATCH];
__device__ unsigned int g_arrive = 0;
__device__ unsigned int g_release = 0;

#define SCAN_BLOCKS 128

__device__ __forceinline__ void grid_barrier(int nblk) {
    __syncthreads();
    if (threadIdx.x == 0) {
        __threadfence();
        unsigned gen = atomicAdd(&g_release, 0u);
        unsigned ticket = atomicAdd(&g_arrive, 1u);
        if (ticket == (unsigned)(nblk - 1)) {
            atomicExch(&g_arrive, 0u);
            __threadfence();
            atomicAdd(&g_release, 1u);
        } else {
            while (*((volatile unsigned int*)&g_release) == gen) {
                __nanosleep(16);
            }
        }
        __threadfence();
    }
    __syncthreads();
}

// ---------------------------------------------------------------------------
// Pre-GEMM (bf16 3-term compensated MMA): gi = x @ Wi + bi.
// M=65536, N=1536, K=512. Tile 128x128x16; 256 threads = 8 warps 4(M)x2(N),
// warp tile 32x64. SMEM holds {hi,lo} interleaved bf16x2 k-pairs (u64):
//   Xs[kp][m] (stride 136), Ws[kp][n] (stride 136). LDS.64 per fragment reg.
// ---------------------------------------------------------------------------
#define GSTRIDE 136

__global__ __launch_bounds__(256) void gemm_gi_tc_kernel(
    const float* __restrict__ X, const float* __restrict__ Wi,
    const float* __restrict__ bi, float* __restrict__ gi)
{
    __shared__ __align__(16) u64 Xs[8 * GSTRIDE];  // 8.5 KB
    __shared__ __align__(16) u64 Ws[8 * GSTRIDE];  // 8.5 KB

    const int m0 = blockIdx.y * 128;
    const int n0 = blockIdx.x * 128;
    const int tid = threadIdx.x;
    const int wid = tid >> 5;
    const int lane = tid & 31;
    const int g = lane >> 2;
    const int tig = lane & 3;
    const int wm = (wid & 3) * 32;
    const int wn = (wid >> 2) * 64;

    // X tile load mapping: row xr (0..127), col base xc in {0,8}
    const int xr = tid >> 1;
    const int xc = (tid & 1) * 8;
    // Wi tile: kp = tid>>5 (0..7), col base nb
    const int wkp = tid >> 5;
    const int nb = (lane) * 4;

    float acc[2][8][4];
#pragma unroll
    for (int mf = 0; mf < 2; mf++)
#pragma unroll
        for (int nf = 0; nf < 8; nf++)
#pragma unroll
            for (int r = 0; r < 4; r++) acc[mf][nf][r] = 0.f;

    for (int k0 = 0; k0 < HDIM; k0 += 16) {
        // X tile: 128 x 16 -> Xs[kp][xr]
#pragma unroll
        for (int h = 0; h < 2; h++) {
            float4 v = *(const float4*)&X[(size_t)(m0 + xr) * HDIM + k0 + xc + h * 4];
            u32 hi0, lo0, hi1, lo1;
            split2_(v.x, v.y, hi0, lo0);
            split2_(v.z, v.w, hi1, lo1);
            Xs[(xc / 2 + h * 2 + 0) * GSTRIDE + xr] = (u64)hi0 | ((u64)lo0 << 32);
            Xs[(xc / 2 + h * 2 + 1) * GSTRIDE + xr] = (u64)hi1 | ((u64)lo1 << 32);
        }
        // Wi tile: 16 x 128 -> Ws[kp][n]; pair packs rows (2kp, 2kp+1)
        {
            float4 r0 = *(const float4*)&Wi[(size_t)(k0 + 2 * wkp) * HDIM3 + n0 + nb];
            float4 r1 = *(const float4*)&Wi[(size_t)(k0 + 2 * wkp + 1) * HDIM3 + n0 + nb];
            float a0[4] = {r0.x, r0.y, r0.z, r0.w};
            float a1[4] = {r1.x, r1.y, r1.z, r1.w};
#pragma unroll
            for (int i = 0; i < 4; i++) {
                u32 hi, lo;
                split2_(a0[i], a1[i], hi, lo);
                Ws[wkp * GSTRIDE + nb + i] = (u64)hi | ((u64)lo << 32);
            }
        }
        __syncthreads();

        // Fragments: A a0:(row g, kp tig) a1:(+8) a2:(kp tig+4) a3:(both)
        u32 ah[2][4], al[2][4];
#pragma unroll
        for (int mf = 0; mf < 2; mf++) {
            int mr = wm + mf * 16 + g;
            u64 d0 = Xs[tig * GSTRIDE + mr];
            u64 d1 = Xs[tig * GSTRIDE + mr + 8];
            u64 d2 = Xs[(tig + 4) * GSTRIDE + mr];
            u64 d3 = Xs[(tig + 4) * GSTRIDE + mr + 8];
            ah[mf][0] = (u32)d0; al[mf][0] = (u32)(d0 >> 32);
            ah[mf][1] = (u32)d1; al[mf][1] = (u32)(d1 >> 32);
            ah[mf][2] = (u32)d2; al[mf][2] = (u32)(d2 >> 32);
            ah[mf][3] = (u32)d3; al[mf][3] = (u32)(d3 >> 32);
        }
#pragma unroll
        for (int nf = 0; nf < 8; nf++) {
            int nc = wn + nf * 8 + g;
            u64 e0 = Ws[tig * GSTRIDE + nc];
            u64 e1 = Ws[(tig + 4) * GSTRIDE + nc];
            u32 bh0 = (u32)e0, bl0 = (u32)(e0 >> 32);
            u32 bh1 = (u32)e1, bl1 = (u32)(e1 >> 32);
#pragma unroll
            for (int mf = 0; mf < 2; mf++) {
                mma_bf16(acc[mf][nf][0], acc[mf][nf][1], acc[mf][nf][2], acc[mf][nf][3],
                         ah[mf][0], ah[mf][1], ah[mf][2], ah[mf][3], bh0, bh1);
                mma_bf16(acc[mf][nf][0], acc[mf][nf][1], acc[mf][nf][2], acc[mf][nf][3],
                         ah[mf][0], ah[mf][1], ah[mf][2], ah[mf][3], bl0, bl1);
                mma_bf16(acc[mf][nf][0], acc[mf][nf][1], acc[mf][nf][2], acc[mf][nf][3],
                         al[mf][0], al[mf][1], al[mf][2], al[mf][3], bh0, bh1);
            }
        }
        __syncthreads();
    }

    // Epilogue (validated layout): c0/c1 at (g, 2tig/+1), c2/c3 at (g+8, ..)
#pragma unroll
    for (int mf = 0; mf < 2; mf++) {
#pragma unroll
        for (int nf = 0; nf < 8; nf++) {
            int n = n0 + wn + nf * 8 + 2 * tig;
            float b0v = bi[n], b1v = bi[n + 1];
            int mA = m0 + wm + mf * 16 + g;
            int mB = mA + 8;
            *(float2*)&gi[(size_t)mA * HDIM3 + n] =
                make_float2(acc[mf][nf][0] + b0v, acc[mf][nf][1] + b1v);
            *(float2*)&gi[(size_t)mB * HDIM3 + n] =
                make_float2(acc[mf][nf][2] + b0v, acc[mf][nf][3] + b1v);
        }
    }
}

// ---------------------------------------------------------------------------
// Persistent scan with tensor-core GEMV: 128 blocks x 256 threads (8 warps).
// Block owns h-cols j0..j0+3 => 12 Wh columns (r|z|n), padded to N=16.
// Per step: gh = h(128x512) @ WhSlice(512x16) via m16n8k16 bf16 3-term MMA.
//   - Wh fragments (hi/lo bf16x2 k-pairs) precomputed once into SMEM.
//   - h read from global g_h2 (k-pair packed {hi,lo}) via LDG.64, prefetch 2.
//   - Warp w covers batch rows 16w..16w+15, both n-frags (n 0..15).
//   - MMA result dumped to smem gh_s (stride 17), then threads 0..127 run
//     the validated fp32 gate code and publish h_{t+1} (fp32 recurrence in
//     registers; bf16-split only feeds the MMA).
// ---------------------------------------------------------------------------
#define SCAN_THREADS 256
#define BS_STRIDE 24      // u64 stride for Wh frag smem (16 cols + pad)
#define GH_STRIDE 17

__device__ __forceinline__ float fast_sigmoid(float x) {
    return 1.0f / (1.0f + __expf(-x));
}
__device__ __forceinline__ float fast_tanh(float x) {
    return 2.0f / (1.0f + __expf(-2.0f * x)) - 1.0f;
}

__global__ __launch_bounds__(SCAN_THREADS) void scan_kernel(
    const float* __restrict__ h0, const float* __restrict__ Wh,
    const float* __restrict__ bhn,
    float* __restrict__ out_h, float* __restrict__ out_ys)
{
    __shared__ __align__(16) u64 Bs[KP_TOTAL * BS_STRIDE];   // 48 KB
    __shared__ __align__(16) float gh_s[BATCH * GH_STRIDE];  // 8.5 KB

    const int tid = threadIdx.x;
    const int wid = tid >> 5;
    const int lane = tid & 31;
    const int g = lane >> 2;
    const int tig = lane & 3;
    const int j0 = blockIdx.x * 4;

    // --- One-time: Wh slice -> bf16-split k-pair fragments in SMEM ---
    {
        int kp = tid;  // 256 threads, 256 k-pairs
#pragma unroll
        for (int n = 12; n < 16; n++) Bs[kp * BS_STRIDE + n] = 0ull;
        for (int c = 0; c < 12; c++) {
            int col = (c >> 2) * HDIM + j0 + (c & 3);
            float w0 = Wh[(size_t)(2 * kp) * HDIM3 + col];
            float w1 = Wh[(size_t)(2 * kp + 1) * HDIM3 + col];
            u32 hi, lo;
            split2_(w0, w1, hi, lo);
            Bs[kp * BS_STRIDE + c] = (u64)hi | ((u64)lo << 32);
        }
    }

    float bn[4], hn[4];
    if (tid < BATCH) {
        int b = tid;
#pragma unroll
        for (int c = 0; c < 4; c++) bn[c] = bhn[j0 + c];
        float4 v = *(const float4*)&h0[(size_t)b * HDIM + j0];
        hn[0] = v.x; hn[1] = v.y; hn[2] = v.z; hn[3] = v.w;
        // publish h0 pairs (kp = j0/2, j0/2+1)
        u32 hi0, lo0, hi1, lo1;
        split2_(hn[0], hn[1], hi0, lo0);
        split2_(hn[2], hn[3], hi1, lo1);
        g_h2[0][(j0 / 2) * BATCH + b]     = (u64)hi0 | ((u64)lo0 << 32);
        g_h2[0][(j0 / 2 + 1) * BATCH + b] = (u64)hi1 | ((u64)lo1 << 32);
    }
    grid_barrier(SCAN_BLOCKS);

    const int mbase = wid * 16;   // this warp's batch-row base

    for (int t = 0; t < T_STEPS; t++) {
        const u64* __restrict__ hp = g_h2[t & 1];

        // early gi loads
        float4 gr, gz, gn;
        if (tid < BATCH) {
            const float* gi = &g_gi[((size_t)t * BATCH + tid) * HDIM3];
            gr = *(const float4*)&gi[j0];
            gz = *(const float4*)&gi[HDIM + j0];
            gn = *(const float4*)&gi[2 * HDIM + j0];
        }

        float acc[2][4];
#pragma unroll
        for (int nf = 0; nf < 2; nf++)
#pragma unroll
            for (int r = 0; r < 4; r++) acc[nf][r] = 0.f;

        // A-frag global addresses: idx(kt) = (kt*8 + tig)*128 + mbase + g
        // a0 = [idx], a1 = [idx+8], a2 = [idx+512], a3 = [idx+520]
        u64 pa[2][4];
        {
            int i0 = tig * BATCH + mbase + g;
            pa[0][0] = hp[i0];       pa[0][1] = hp[i0 + 8];
            pa[0][2] = hp[i0 + 512]; pa[0][3] = hp[i0 + 520];
            int i1 = i0 + 8 * BATCH;
            pa[1][0] = hp[i1];       pa[1][1] = hp[i1 + 8];
            pa[1][2] = hp[i1 + 512]; pa[1][3] = hp[i1 + 520];
        }

#pragma unroll 4
        for (int kt = 0; kt < 32; kt++) {
            u64 d0 = pa[kt & 1][0], d1 = pa[kt & 1][1];
            u64 d2 = pa[kt & 1][2], d3 = pa[kt & 1][3];
            if (kt + 2 < 32) {
                int ix = ((kt + 2) * 8 + tig) * BATCH + mbase + g;
                pa[kt & 1][0] = hp[ix];       pa[kt & 1][1] = hp[ix + 8];
                pa[kt & 1][2] = hp[ix + 512]; pa[kt & 1][3] = hp[ix + 520];
            }
            u32 ah0 = (u32)d0, al0 = (u32)(d0 >> 32);
            u32 ah1 = (u32)d1, al1 = (u32)(d1 >> 32);
            u32 ah2 = (u32)d2, al2 = (u32)(d2 >> 32);
            u32 ah3 = (u32)d3, al3 = (u32)(d3 >> 32);
#pragma unroll
            for (int nf = 0; nf < 2; nf++) {
                u64 e0 = Bs[(kt * 8 + tig) * BS_STRIDE + nf * 8 + g];
                u64 e1 = Bs[(kt * 8 + tig + 4) * BS_STRIDE + nf * 8 + g];
                u32 bh0 = (u32)e0, bl0 = (u32)(e0 >> 32);
                u32 bh1 = (u32)e1, bl1 = (u32)(e1 >> 32);
                mma_bf16(acc[nf][0], acc[nf][1], acc[nf][2], acc[nf][3],
                         ah0, ah1, ah2, ah3, bh0, bh1);
                mma_bf16(acc[nf][0], acc[nf][1], acc[nf][2], acc[nf][3],
                         ah0, ah1, ah2, ah3, bl0, bl1);
                mma_bf16(acc[nf][0], acc[nf][1], acc[nf][2], acc[nf][3],
                         al0, al1, al2, al3, bh0, bh1);
            }
        }

        // Dump gh fragments: rows mbase+g(+8), cols nf*8 + 2tig(+1)
#pragma unroll
        for (int nf = 0; nf < 2; nf++) {
            int cb = nf * 8 + 2 * tig;
            gh_s[(mbase + g) * GH_STRIDE + cb]     = acc[nf][0];
            gh_s[(mbase + g) * GH_STRIDE + cb + 1] = acc[nf][1];
            gh_s[(mbase + g + 8) * GH_STRIDE + cb]     = acc[nf][2];
            gh_s[(mbase + g + 8) * GH_STRIDE + cb + 1] = acc[nf][3];
        }
        __syncthreads();

        if (tid < BATCH) {
            int b = tid;
            float a[12];
#pragma unroll
            for (int c = 0; c < 12; c++) a[c] = gh_s[b * GH_STRIDE + c];

            float giR[4] = {gr.x, gr.y, gr.z, gr.w};
            float giZ[4] = {gz.x, gz.y, gz.z, gz.w};
            float giN[4] = {gn.x, gn.y, gn.z, gn.w};

#pragma unroll
            for (int c = 0; c < 4; c++) {
                float r = fast_sigmoid(giR[c] + a[c]);
                float z = fast_sigmoid(giZ[c] + a[4 + c]);
                float n = fast_tanh(giN[c] + r * (a[8 + c] + bn[c]));
                hn[c] = (1.0f - z) * n + z * hn[c];
            }

            *(float4*)&out_ys[((size_t)t * BATCH + b) * HDIM + j0] =
                make_float4(hn[0], hn[1], hn[2], hn[3]);

            u64* __restrict__ hq = g_h2[(t & 1) ^ 1];
            u32 hi0, lo0, hi1, lo1;
            split2_(hn[0], hn[1], hi0, lo0);
            split2_(hn[2], hn[3], hi1, lo1);
            hq[(j0 / 2) * BATCH + b]     = (u64)hi0 | ((u64)lo0 << 32);
            hq[(j0 / 2 + 1) * BATCH + b] = (u64)hi1 | ((u64)lo1 << 32);
        }

        grid_barrier(SCAN_BLOCKS);
    }

    if (out_h && tid < BATCH) {
        *(float4*)&out_h[(size_t)tid * HDIM + j0] =
            make_float4(hn[0], hn[1], hn[2], hn[3]);
    }
}

// ---------------------------------------------------------------------------
// kernel_launch: inputs per metadata order: x, h0, Wi, bi, Wh, bhn
// ---------------------------------------------------------------------------
extern "C" void kernel_launch(void* const* d_in, const int* in_sizes, int n_in,
                              void* d_out, int out_size)
{
    const float* x   = (const float*)d_in[0];   // [T, B, H]
    const float* h0  = (const float*)d_in[1];   // [B, H]
    const float* Wi  = (const float*)d_in[2];   // [H, 3H]
    const float* bi  = (const float*)d_in[3];   // [3H]
    const float* Wh  = (const float*)d_in[4];   // [H, 3H]
    const float* bhn = (const float*)d_in[5];   // [H]

    float* out = (float*)d_out;
    float* out_h;
    float* out_ys;
    const long long ys_elems = (long long)T_STEPS * BATCH * HDIM;
    if ((long long)out_size >= ys_elems + (long long)BATCH * HDIM) {
        out_h = out;                    // (h_final, ys) flattened in order
        out_ys = out + (size_t)BATCH * HDIM;
    } else {
        out_h = nullptr;                // ys only
        out_ys = out;
    }

    float* gi;
    cudaGetSymbolAddress((void**)&gi, g_gi);

    // 1) gi = x @ Wi + bi  (bf16 3-term compensated tensor-core GEMM)
    dim3 ggrid(HDIM3 / 128, (T_STEPS * BATCH) / 128);
    gemm_gi_tc_kernel<<<ggrid, 256>>>(x, Wi, bi, gi);

    // 2) persistent GRU scan (tensor-core per-step GEMV)
    scan_kernel<<<SCAN_BLOCKS, SCAN_THREADS>>>(h0, Wh, bhn, out_h, out_ys);
}

// round 12
// speedup vs baseline: 1.4776x; 1.2493x over previous
#include <cuda_runtime.h>
#include <cuda_bf16.h>
#include <math.h>

// Problem constants
#define T_STEPS 512
#define BATCH   128
#define HDIM    512
#define HDIM3   1536

typedef unsigned long long u64;
typedef unsigned int u32;

// ---------------------------------------------------------------------------
// bf16 helpers: pack two floats' bf16 into one u32 (f0 -> low 16, f1 -> high).
// split2: hi/lo bf16 decomposition of two floats, packed as k-pairs.
// ---------------------------------------------------------------------------
__device__ __forceinline__ u32 pkbf_(float f0, float f1) {
    unsigned short s0 = __bfloat16_as_ushort(__float2bfloat16_rn(f0));
    unsigned short s1 = __bfloat16_as_ushort(__float2bfloat16_rn(f1));
    return (u32)s0 | ((u32)s1 << 16);
}
__device__ __forceinline__ void split2_(float f0, float f1, u32& hi, u32& lo) {
    __nv_bfloat16 h0 = __float2bfloat16_rn(f0);
    __nv_bfloat16 h1 = __float2bfloat16_rn(f1);
    float r0 = f0 - __bfloat162float(h0);
    float r1 = f1 - __bfloat162float(h1);
    hi = (u32)__bfloat16_as_ushort(h0) | ((u32)__bfloat16_as_ushort(h1) << 16);
    lo = pkbf_(r0, r1);
}

// m16n8k16 bf16 MMA, fp32 accumulate (fragment layouts per PTX ISA).
__device__ __forceinline__ void mma_bf16(
    float& d0, float& d1, float& d2, float& d3,
    u32 a0, u32 a1, u32 a2, u32 a3, u32 b0, u32 b1)
{
    asm volatile(
        "mma.sync.aligned.m16n8k16.row.col.f32.bf16.bf16.f32 "
        "{%0,%1,%2,%3}, {%4,%5,%6,%7}, {%8,%9}, {%0,%1,%2,%3};"
        : "+f"(d0), "+f"(d1), "+f"(d2), "+f"(d3)
        : "r"(a0), "r"(a1), "r"(a2), "r"(a3), "r"(b0), "r"(b1));
}

// ---------------------------------------------------------------------------
// Scratch: gi [T,B,3H] fp32; h ping-pong as k-pair packed {hi,lo} bf16x2:
// g_h2[buf][kp*128 + b]. Barrier counters (sense-reversing, self-resetting).
// ---------------------------------------------------------------------------
#define KP_TOTAL 256   // 512 k / 2 per pair
__device__ __align__(16) float g_gi[(size_t)T_STEPS * BATCH * HDIM3];
__device__ __align__(16) u64 g_h2[2][KP_TOTAL * BATCH];
__device__ unsigned int g_arrive = 0;
__device__ unsigned int g_release = 0;

#define SCAN_BLOCKS 128

__device__ __forceinline__ void grid_barrier(int nblk) {
    __syncthreads();
    if (threadIdx.x == 0) {
        __threadfence();
        unsigned gen = atomicAdd(&g_release, 0u);
        unsigned ticket = atomicAdd(&g_arrive, 1u);
        if (ticket == (unsigned)(nblk - 1)) {
            atomicExch(&g_arrive, 0u);
            __threadfence();
            atomicAdd(&g_release, 1u);
        } else {
            while (*((volatile unsigned int*)&g_release) == gen) {
                __nanosleep(16);
            }
        }
        __threadfence();
    }
    __syncthreads();
}

// ---------------------------------------------------------------------------
// Pre-GEMM (bf16 3-term compensated MMA): gi = x @ Wi + bi.  (validated R8)
// ---------------------------------------------------------------------------
#define GSTRIDE 136

__global__ __launch_bounds__(256) void gemm_gi_tc_kernel(
    const float* __restrict__ X, const float* __restrict__ Wi,
    const float* __restrict__ bi, float* __restrict__ gi)
{
    __shared__ __align__(16) u64 Xs[8 * GSTRIDE];
    __shared__ __align__(16) u64 Ws[8 * GSTRIDE];

    const int m0 = blockIdx.y * 128;
    const int n0 = blockIdx.x * 128;
    const int tid = threadIdx.x;
    const int wid = tid >> 5;
    const int lane = tid & 31;
    const int g = lane >> 2;
    const int tig = lane & 3;
    const int wm = (wid & 3) * 32;
    const int wn = (wid >> 2) * 64;

    const int xr = tid >> 1;
    const int xc = (tid & 1) * 8;
    const int wkp = tid >> 5;
    const int nb = (lane) * 4;

    float acc[2][8][4];
#pragma unroll
    for (int mf = 0; mf < 2; mf++)
#pragma unroll
        for (int nf = 0; nf < 8; nf++)
#pragma unroll
            for (int r = 0; r < 4; r++) acc[mf][nf][r] = 0.f;

    for (int k0 = 0; k0 < HDIM; k0 += 16) {
#pragma unroll
        for (int h = 0; h < 2; h++) {
            float4 v = *(const float4*)&X[(size_t)(m0 + xr) * HDIM + k0 + xc + h * 4];
            u32 hi0, lo0, hi1, lo1;
            split2_(v.x, v.y, hi0, lo0);
            split2_(v.z, v.w, hi1, lo1);
            Xs[(xc / 2 + h * 2 + 0) * GSTRIDE + xr] = (u64)hi0 | ((u64)lo0 << 32);
            Xs[(xc / 2 + h * 2 + 1) * GSTRIDE + xr] = (u64)hi1 | ((u64)lo1 << 32);
        }
        {
            float4 r0 = *(const float4*)&Wi[(size_t)(k0 + 2 * wkp) * HDIM3 + n0 + nb];
            float4 r1 = *(const float4*)&Wi[(size_t)(k0 + 2 * wkp + 1) * HDIM3 + n0 + nb];
            float a0[4] = {r0.x, r0.y, r0.z, r0.w};
            float a1[4] = {r1.x, r1.y, r1.z, r1.w};
#pragma unroll
            for (int i = 0; i < 4; i++) {
                u32 hi, lo;
                split2_(a0[i], a1[i], hi, lo);
                Ws[wkp * GSTRIDE + nb + i] = (u64)hi | ((u64)lo << 32);
            }
        }
        __syncthreads();

        u32 ah[2][4], al[2][4];
#pragma unroll
        for (int mf = 0; mf < 2; mf++) {
            int mr = wm + mf * 16 + g;
            u64 d0 = Xs[tig * GSTRIDE + mr];
            u64 d1 = Xs[tig * GSTRIDE + mr + 8];
            u64 d2 = Xs[(tig + 4) * GSTRIDE + mr];
            u64 d3 = Xs[(tig + 4) * GSTRIDE + mr + 8];
            ah[mf][0] = (u32)d0; al[mf][0] = (u32)(d0 >> 32);
            ah[mf][1] = (u32)d1; al[mf][1] = (u32)(d1 >> 32);
            ah[mf][2] = (u32)d2; al[mf][2] = (u32)(d2 >> 32);
            ah[mf][3] = (u32)d3; al[mf][3] = (u32)(d3 >> 32);
        }
#pragma unroll
        for (int nf = 0; nf < 8; nf++) {
            int nc = wn + nf * 8 + g;
            u64 e0 = Ws[tig * GSTRIDE + nc];
            u64 e1 = Ws[(tig + 4) * GSTRIDE + nc];
            u32 bh0 = (u32)e0, bl0 = (u32)(e0 >> 32);
            u32 bh1 = (u32)e1, bl1 = (u32)(e1 >> 32);
#pragma unroll
            for (int mf = 0; mf < 2; mf++) {
                mma_bf16(acc[mf][nf][0], acc[mf][nf][1], acc[mf][nf][2], acc[mf][nf][3],
                         ah[mf][0], ah[mf][1], ah[mf][2], ah[mf][3], bh0, bh1);
                mma_bf16(acc[mf][nf][0], acc[mf][nf][1], acc[mf][nf][2], acc[mf][nf][3],
                         ah[mf][0], ah[mf][1], ah[mf][2], ah[mf][3], bl0, bl1);
                mma_bf16(acc[mf][nf][0], acc[mf][nf][1], acc[mf][nf][2], acc[mf][nf][3],
                         al[mf][0], al[mf][1], al[mf][2], al[mf][3], bh0, bh1);
            }
        }
        __syncthreads();
    }

#pragma unroll
    for (int mf = 0; mf < 2; mf++) {
#pragma unroll
        for (int nf = 0; nf < 8; nf++) {
            int n = n0 + wn + nf * 8 + 2 * tig;
            float b0v = bi[n], b1v = bi[n + 1];
            int mA = m0 + wm + mf * 16 + g;
            int mB = mA + 8;
            *(float2*)&gi[(size_t)mA * HDIM3 + n] =
                make_float2(acc[mf][nf][0] + b0v, acc[mf][nf][1] + b1v);
            *(float2*)&gi[(size_t)mB * HDIM3 + n] =
                make_float2(acc[mf][nf][2] + b0v, acc[mf][nf][3] + b1v);
        }
    }
}

// ---------------------------------------------------------------------------
// Persistent scan (R8 structure, validated): 128 blocks x 256 threads.
// Block owns h-cols j0..j0+3 => 12 Wh columns padded to N=16 (2 n-frags).
// Changes vs R8 (only two):
//   * BS_STRIDE 24 -> 20: LDS.64 banks (40*tig + 2g) mod 32 tile all 32
//     banks per 16-lane phase -> conflict-free (was 4-way).
//   * Prefetch ring depth 2 -> 4: covers ~4 iterations of L2 latency.
// ---------------------------------------------------------------------------
#define SCAN_THREADS 256
#define BS_STRIDE 20      // u64; conflict-free B-frag loads
#define GH_STRIDE 17
#define PD 4              // prefetch depth (ring)

__device__ __forceinline__ float fast_sigmoid(float x) {
    return 1.0f / (1.0f + __expf(-x));
}
__device__ __forceinline__ float fast_tanh(float x) {
    return 2.0f / (1.0f + __expf(-2.0f * x)) - 1.0f;
}

__global__ __launch_bounds__(SCAN_THREADS) void scan_kernel(
    const float* __restrict__ h0, const float* __restrict__ Wh,
    const float* __restrict__ bhn,
    float* __restrict__ out_h, float* __restrict__ out_ys)
{
    __shared__ __align__(16) u64 Bs[KP_TOTAL * BS_STRIDE];   // 40 KB
    __shared__ __align__(16) float gh_s[BATCH * GH_STRIDE];  // 8.5 KB

    const int tid = threadIdx.x;
    const int wid = tid >> 5;
    const int lane = tid & 31;
    const int g = lane >> 2;
    const int tig = lane & 3;
    const int j0 = blockIdx.x * 4;

    // --- One-time: Wh slice -> bf16-split k-pair fragments in SMEM ---
    {
        int kp = tid;  // 256 threads, 256 k-pairs
#pragma unroll
        for (int n = 12; n < 16; n++) Bs[kp * BS_STRIDE + n] = 0ull;
        for (int c = 0; c < 12; c++) {
            int col = (c >> 2) * HDIM + j0 + (c & 3);
            float w0 = Wh[(size_t)(2 * kp) * HDIM3 + col];
            float w1 = Wh[(size_t)(2 * kp + 1) * HDIM3 + col];
            u32 hi, lo;
            split2_(w0, w1, hi, lo);
            Bs[kp * BS_STRIDE + c] = (u64)hi | ((u64)lo << 32);
        }
    }

    float bn[4], hn[4];
    if (tid < BATCH) {
        int b = tid;
#pragma unroll
        for (int c = 0; c < 4; c++) bn[c] = bhn[j0 + c];
        float4 v = *(const float4*)&h0[(size_t)b * HDIM + j0];
        hn[0] = v.x; hn[1] = v.y; hn[2] = v.z; hn[3] = v.w;
        u32 hi0, lo0, hi1, lo1;
        split2_(hn[0], hn[1], hi0, lo0);
        split2_(hn[2], hn[3], hi1, lo1);
        g_h2[0][(j0 / 2) * BATCH + b]     = (u64)hi0 | ((u64)lo0 << 32);
        g_h2[0][(j0 / 2 + 1) * BATCH + b] = (u64)hi1 | ((u64)lo1 << 32);
    }
    grid_barrier(SCAN_BLOCKS);

    const int mbase = wid * 16;   // this warp's batch-row base

    for (int t = 0; t < T_STEPS; t++) {
        const u64* __restrict__ hp = g_h2[t & 1];

        // early gi loads
        float4 gr, gz, gn;
        if (tid < BATCH) {
            const float* gi = &g_gi[((size_t)t * BATCH + tid) * HDIM3];
            gr = *(const float4*)&gi[j0];
            gz = *(const float4*)&gi[HDIM + j0];
            gn = *(const float4*)&gi[2 * HDIM + j0];
        }

        float acc[2][4];
#pragma unroll
        for (int nf = 0; nf < 2; nf++)
#pragma unroll
            for (int r = 0; r < 4; r++) acc[nf][r] = 0.f;

        // A-frag prefetch ring, depth PD=4.
        // idx(kt) = (kt*8 + tig)*128 + mbase + g; a1=+8(row), a2=+512, a3=+520
        u64 pa[PD][4];
#pragma unroll
        for (int p = 0; p < PD; p++) {
            int ix = (p * 8 + tig) * BATCH + mbase + g;
            pa[p][0] = hp[ix];       pa[p][1] = hp[ix + 8];
            pa[p][2] = hp[ix + 512]; pa[p][3] = hp[ix + 520];
        }

#pragma unroll 4
        for (int kt = 0; kt < 32; kt++) {
            const int s = kt & (PD - 1);
            u64 d0 = pa[s][0], d1 = pa[s][1], d2 = pa[s][2], d3 = pa[s][3];
            if (kt + PD < 32) {
                int ix = ((kt + PD) * 8 + tig) * BATCH + mbase + g;
                pa[s][0] = hp[ix];       pa[s][1] = hp[ix + 8];
                pa[s][2] = hp[ix + 512]; pa[s][3] = hp[ix + 520];
            }
            u32 ah0 = (u32)d0, al0 = (u32)(d0 >> 32);
            u32 ah1 = (u32)d1, al1 = (u32)(d1 >> 32);
            u32 ah2 = (u32)d2, al2 = (u32)(d2 >> 32);
            u32 ah3 = (u32)d3, al3 = (u32)(d3 >> 32);
#pragma unroll
            for (int nf = 0; nf < 2; nf++) {
                u64 e0 = Bs[(kt * 8 + tig) * BS_STRIDE + nf * 8 + g];
                u64 e1 = Bs[(kt * 8 + tig + 4) * BS_STRIDE + nf * 8 + g];
                u32 bh0 = (u32)e0, bl0 = (u32)(e0 >> 32);
                u32 bh1 = (u32)e1, bl1 = (u32)(e1 >> 32);
                mma_bf16(acc[nf][0], acc[nf][1], acc[nf][2], acc[nf][3],
                         ah0, ah1, ah2, ah3, bh0, bh1);
                mma_bf16(acc[nf][0], acc[nf][1], acc[nf][2], acc[nf][3],
                         ah0, ah1, ah2, ah3, bl0, bl1);
                mma_bf16(acc[nf][0], acc[nf][1], acc[nf][2], acc[nf][3],
                         al0, al1, al2, al3, bh0, bh1);
            }
        }

        // Dump gh fragments: rows mbase+g(+8), cols nf*8 + 2tig(+1)
#pragma unroll
        for (int nf = 0; nf < 2; nf++) {
            int cb = nf * 8 + 2 * tig;
            gh_s[(mbase + g) * GH_STRIDE + cb]         = acc[nf][0];
            gh_s[(mbase + g) * GH_STRIDE + cb + 1]     = acc[nf][1];
            gh_s[(mbase + g + 8) * GH_STRIDE + cb]     = acc[nf][2];
            gh_s[(mbase + g + 8) * GH_STRIDE + cb + 1] = acc[nf][3];
        }
        __syncthreads();

        if (tid < BATCH) {
            int b = tid;
            float a[12];
#pragma unroll
            for (int c = 0; c < 12; c++) a[c] = gh_s[b * GH_STRIDE + c];

            float giR[4] = {gr.x, gr.y, gr.z, gr.w};
            float giZ[4] = {gz.x, gz.y, gz.z, gz.w};
            float giN[4] = {gn.x, gn.y, gn.z, gn.w};

#pragma unroll
            for (int c = 0; c < 4; c++) {
                float r = fast_sigmoid(giR[c] + a[c]);
                float z = fast_sigmoid(giZ[c] + a[4 + c]);
                float n = fast_tanh(giN[c] + r * (a[8 + c] + bn[c]));
                hn[c] = (1.0f - z) * n + z * hn[c];
            }

            *(float4*)&out_ys[((size_t)t * BATCH + b) * HDIM + j0] =
                make_float4(hn[0], hn[1], hn[2], hn[3]);

            u64* __restrict__ hq = g_h2[(t & 1) ^ 1];
            u32 hi0, lo0, hi1, lo1;
            split2_(hn[0], hn[1], hi0, lo0);
            split2_(hn[2], hn[3], hi1, lo1);
            hq[(j0 / 2) * BATCH + b]     = (u64)hi0 | ((u64)lo0 << 32);
            hq[(j0 / 2 + 1) * BATCH + b] = (u64)hi1 | ((u64)lo1 << 32);
        }

        grid_barrier(SCAN_BLOCKS);
    }

    if (out_h && tid < BATCH) {
        *(float4*)&out_h[(size_t)tid * HDIM + j0] =
            make_float4(hn[0], hn[1], hn[2], hn[3]);
    }
}

// ---------------------------------------------------------------------------
// kernel_launch: inputs per metadata order: x, h0, Wi, bi, Wh, bhn
// ---------------------------------------------------------------------------
extern "C" void kernel_launch(void* const* d_in, const int* in_sizes, int n_in,
                              void* d_out, int out_size)
{
    const float* x   = (const float*)d_in[0];   // [T, B, H]
    const float* h0  = (const float*)d_in[1];   // [B, H]
    const float* Wi  = (const float*)d_in[2];   // [H, 3H]
    const float* bi  = (const float*)d_in[3];   // [3H]
    const float* Wh  = (const float*)d_in[4];   // [H, 3H]
    const float* bhn = (const float*)d_in[5];   // [H]

    float* out = (float*)d_out;
    float* out_h;
    float* out_ys;
    const long long ys_elems = (long long)T_STEPS * BATCH * HDIM;
    if ((long long)out_size >= ys_elems + (long long)BATCH * HDIM) {
        out_h = out;                    // (h_final, ys) flattened in order
        out_ys = out + (size_t)BATCH * HDIM;
    } else {
        out_h = nullptr;                // ys only
        out_ys = out;
    }

    float* gi;
    cudaGetSymbolAddress((void**)&gi, g_gi);

    // 1) gi = x @ Wi + bi  (bf16 3-term compensated tensor-core GEMM)
    dim3 ggrid(HDIM3 / 128, (T_STEPS * BATCH) / 128);
    gemm_gi_tc_kernel<<<ggrid, 256>>>(x, Wi, bi, gi);

    // 2) persistent GRU scan (tensor-core per-step GEMV)
    scan_kernel<<<SCAN_BLOCKS, SCAN_THREADS>>>(h0, Wh, bhn, out_h, out_ys);
}

// round 13
// speedup vs baseline: 1.6166x; 1.0941x over previous
#include <cuda_runtime.h>
#include <cuda_bf16.h>
#include <math.h>

// Problem constants
#define T_STEPS 512
#define BATCH   128
#define HDIM    512
#define HDIM3   1536

typedef unsigned long long u64;
typedef unsigned int u32;

// ---------------------------------------------------------------------------
// bf16 helpers
// ---------------------------------------------------------------------------
__device__ __forceinline__ u32 pkbf_(float f0, float f1) {
    unsigned short s0 = __bfloat16_as_ushort(__float2bfloat16_rn(f0));
    unsigned short s1 = __bfloat16_as_ushort(__float2bfloat16_rn(f1));
    return (u32)s0 | ((u32)s1 << 16);
}
__device__ __forceinline__ void split2_(float f0, float f1, u32& hi, u32& lo) {
    __nv_bfloat16 h0 = __float2bfloat16_rn(f0);
    __nv_bfloat16 h1 = __float2bfloat16_rn(f1);
    float r0 = f0 - __bfloat162float(h0);
    float r1 = f1 - __bfloat162float(h1);
    hi = (u32)__bfloat16_as_ushort(h0) | ((u32)__bfloat16_as_ushort(h1) << 16);
    lo = pkbf_(r0, r1);
}

// m16n8k16 bf16 MMA, fp32 accumulate.
__device__ __forceinline__ void mma_bf16(
    float& d0, float& d1, float& d2, float& d3,
    u32 a0, u32 a1, u32 a2, u32 a3, u32 b0, u32 b1)
{
    asm volatile(
        "mma.sync.aligned.m16n8k16.row.col.f32.bf16.bf16.f32 "
        "{%0,%1,%2,%3}, {%4,%5,%6,%7}, {%8,%9}, {%0,%1,%2,%3};"
        : "+f"(d0), "+f"(d1), "+f"(d2), "+f"(d3)
        : "r"(a0), "r"(a1), "r"(a2), "r"(a3), "r"(b0), "r"(b1));
}

// ---------------------------------------------------------------------------
// Scratch + barrier state
// ---------------------------------------------------------------------------
#define KP_TOTAL 256   // 512 k / 2 per pair
__device__ __align__(16) float g_gi[(size_t)T_STEPS * BATCH * HDIM3];
__device__ __align__(16) u64 g_h2[2][KP_TOTAL * BATCH];
__device__ unsigned int g_arrive = 0;
__device__ unsigned int g_release = 0;

#define SCAN_BLOCKS 128

// Lean sense-reversing grid barrier (acq_rel semantics; R6-validated pattern).
__device__ __forceinline__ void grid_barrier(int nblk) {
    __syncthreads();
    if (threadIdx.x == 0) {
        unsigned gen;
        asm volatile("ld.acquire.gpu.u32 %0, [%1];"
                     : "=r"(gen) : "l"(&g_release) : "memory");
        unsigned ticket;
        asm volatile("atom.acq_rel.gpu.add.u32 %0, [%1], 1;"
                     : "=r"(ticket) : "l"(&g_arrive) : "memory");
        if (ticket == (unsigned)(nblk - 1)) {
            asm volatile("st.relaxed.gpu.u32 [%0], 0;"
                         :: "l"(&g_arrive) : "memory");
            unsigned dummy;
            asm volatile("atom.release.gpu.add.u32 %0, [%1], 1;"
                         : "=r"(dummy) : "l"(&g_release) : "memory");
        } else {
            unsigned r;
            while (1) {
                asm volatile("ld.acquire.gpu.u32 %0, [%1];"
                             : "=r"(r) : "l"(&g_release) : "memory");
                if (r != gen) break;
                __nanosleep(16);
            }
        }
    }
    __syncthreads();
}

// ---------------------------------------------------------------------------
// Pre-GEMM (bf16 3-term compensated MMA): gi = x @ Wi + bi.
// Only change vs R12: GSTRIDE 136 -> 132 (conflict-free fragment LDS.64).
// ---------------------------------------------------------------------------
#define GSTRIDE 132

__global__ __launch_bounds__(256) void gemm_gi_tc_kernel(
    const float* __restrict__ X, const float* __restrict__ Wi,
    const float* __restrict__ bi, float* __restrict__ gi)
{
    __shared__ __align__(16) u64 Xs[8 * GSTRIDE];
    __shared__ __align__(16) u64 Ws[8 * GSTRIDE];

    const int m0 = blockIdx.y * 128;
    const int n0 = blockIdx.x * 128;
    const int tid = threadIdx.x;
    const int wid = tid >> 5;
    const int lane = tid & 31;
    const int g = lane >> 2;
    const int tig = lane & 3;
    const int wm = (wid & 3) * 32;
    const int wn = (wid >> 2) * 64;

    const int xr = tid >> 1;
    const int xc = (tid & 1) * 8;
    const int wkp = tid >> 5;
    const int nb = (lane) * 4;

    float acc[2][8][4];
#pragma unroll
    for (int mf = 0; mf < 2; mf++)
#pragma unroll
        for (int nf = 0; nf < 8; nf++)
#pragma unroll
            for (int r = 0; r < 4; r++) acc[mf][nf][r] = 0.f;

    for (int k0 = 0; k0 < HDIM; k0 += 16) {
#pragma unroll
        for (int h = 0; h < 2; h++) {
            float4 v = *(const float4*)&X[(size_t)(m0 + xr) * HDIM + k0 + xc + h * 4];
            u32 hi0, lo0, hi1, lo1;
            split2_(v.x, v.y, hi0, lo0);
            split2_(v.z, v.w, hi1, lo1);
            Xs[(xc / 2 + h * 2 + 0) * GSTRIDE + xr] = (u64)hi0 | ((u64)lo0 << 32);
            Xs[(xc / 2 + h * 2 + 1) * GSTRIDE + xr] = (u64)hi1 | ((u64)lo1 << 32);
        }
        {
            float4 r0 = *(const float4*)&Wi[(size_t)(k0 + 2 * wkp) * HDIM3 + n0 + nb];
            float4 r1 = *(const float4*)&Wi[(size_t)(k0 + 2 * wkp + 1) * HDIM3 + n0 + nb];
            float a0[4] = {r0.x, r0.y, r0.z, r0.w};
            float a1[4] = {r1.x, r1.y, r1.z, r1.w};
#pragma unroll
            for (int i = 0; i < 4; i++) {
                u32 hi, lo;
                split2_(a0[i], a1[i], hi, lo);
                Ws[wkp * GSTRIDE + nb + i] = (u64)hi | ((u64)lo << 32);
            }
        }
        __syncthreads();

        u32 ah[2][4], al[2][4];
#pragma unroll
        for (int mf = 0; mf < 2; mf++) {
            int mr = wm + mf * 16 + g;
            u64 d0 = Xs[tig * GSTRIDE + mr];
            u64 d1 = Xs[tig * GSTRIDE + mr + 8];
            u64 d2 = Xs[(tig + 4) * GSTRIDE + mr];
            u64 d3 = Xs[(tig + 4) * GSTRIDE + mr + 8];
            ah[mf][0] = (u32)d0; al[mf][0] = (u32)(d0 >> 32);
            ah[mf][1] = (u32)d1; al[mf][1] = (u32)(d1 >> 32);
            ah[mf][2] = (u32)d2; al[mf][2] = (u32)(d2 >> 32);
            ah[mf][3] = (u32)d3; al[mf][3] = (u32)(d3 >> 32);
        }
#pragma unroll
        for (int nf = 0; nf < 8; nf++) {
            int nc = wn + nf * 8 + g;
            u64 e0 = Ws[tig * GSTRIDE + nc];
            u64 e1 = Ws[(tig + 4) * GSTRIDE + nc];
            u32 bh0 = (u32)e0, bl0 = (u32)(e0 >> 32);
            u32 bh1 = (u32)e1, bl1 = (u32)(e1 >> 32);
#pragma unroll
            for (int mf = 0; mf < 2; mf++) {
                mma_bf16(acc[mf][nf][0], acc[mf][nf][1], acc[mf][nf][2], acc[mf][nf][3],
                         ah[mf][0], ah[mf][1], ah[mf][2], ah[mf][3], bh0, bh1);
                mma_bf16(acc[mf][nf][0], acc[mf][nf][1], acc[mf][nf][2], acc[mf][nf][3],
                         ah[mf][0], ah[mf][1], ah[mf][2], ah[mf][3], bl0, bl1);
                mma_bf16(acc[mf][nf][0], acc[mf][nf][1], acc[mf][nf][2], acc[mf][nf][3],
                         al[mf][0], al[mf][1], al[mf][2], al[mf][3], bh0, bh1);
            }
        }
        __syncthreads();
    }

#pragma unroll
    for (int mf = 0; mf < 2; mf++) {
#pragma unroll
        for (int nf = 0; nf < 8; nf++) {
            int n = n0 + wn + nf * 8 + 2 * tig;
            float b0v = bi[n], b1v = bi[n + 1];
            int mA = m0 + wm + mf * 16 + g;
            int mB = mA + 8;
            *(float2*)&gi[(size_t)mA * HDIM3 + n] =
                make_float2(acc[mf][nf][0] + b0v, acc[mf][nf][1] + b1v);
            *(float2*)&gi[(size_t)mB * HDIM3 + n] =
                make_float2(acc[mf][nf][2] + b0v, acc[mf][nf][3] + b1v);
        }
    }
}

// ---------------------------------------------------------------------------
// Persistent scan: 128 blocks x 256 threads; shuffle-based gate epilogue.
// Lane (wid, g, tig): row = wid*16 + g + (tig>=2 ? 8 : 0); gate-col pair
// jc = 2*(tig&1). After the MMA loop, shfl_xor(·,2) exchanges fragments so
// every lane holds r,z,n for its 2 gate columns — no smem, no syncthreads.
// ---------------------------------------------------------------------------
#define SCAN_THREADS 256
#define BS_STRIDE 20      // u64; conflict-free B-frag loads
#define PD 4              // prefetch depth (ring)

__device__ __forceinline__ float fast_sigmoid(float x) {
    return 1.0f / (1.0f + __expf(-x));
}
__device__ __forceinline__ float fast_tanh(float x) {
    return 2.0f / (1.0f + __expf(-2.0f * x)) - 1.0f;
}

__global__ __launch_bounds__(SCAN_THREADS) void scan_kernel(
    const float* __restrict__ h0, const float* __restrict__ Wh,
    const float* __restrict__ bhn,
    float* __restrict__ out_h, float* __restrict__ out_ys)
{
    __shared__ __align__(16) u64 Bs[KP_TOTAL * BS_STRIDE];   // 40 KB

    const int tid = threadIdx.x;
    const int wid = tid >> 5;
    const int lane = tid & 31;
    const int g = lane >> 2;
    const int tig = lane & 3;
    const int j0 = blockIdx.x * 4;

    // --- One-time: Wh slice -> bf16-split k-pair fragments in SMEM ---
    {
        int kp = tid;  // 256 threads, 256 k-pairs
#pragma unroll
        for (int n = 12; n < 16; n++) Bs[kp * BS_STRIDE + n] = 0ull;
        for (int c = 0; c < 12; c++) {
            int col = (c >> 2) * HDIM + j0 + (c & 3);
            float w0 = Wh[(size_t)(2 * kp) * HDIM3 + col];
            float w1 = Wh[(size_t)(2 * kp + 1) * HDIM3 + col];
            u32 hi, lo;
            split2_(w0, w1, hi, lo);
            Bs[kp * BS_STRIDE + c] = (u64)hi | ((u64)lo << 32);
        }
    }

    // Lane's gate assignment
    const int row = wid * 16 + g + ((tig & 2) << 2);  // +8 for tig>=2
    const int jc = (tig & 1) * 2;                     // col pair base (0 or 2)
    const int jcol = j0 + jc;
    const int kp_out = j0 / 2 + (tig & 1);

    float bn0 = bhn[jcol], bn1 = bhn[jcol + 1];
    float hn0, hn1;
    {
        float2 v = *(const float2*)&h0[(size_t)row * HDIM + jcol];
        hn0 = v.x; hn1 = v.y;
        u32 hi, lo;
        split2_(hn0, hn1, hi, lo);
        g_h2[0][kp_out * BATCH + row] = (u64)hi | ((u64)lo << 32);
    }
    grid_barrier(SCAN_BLOCKS);

    const int mbase = wid * 16;   // warp's batch-row base for MMA

    for (int t = 0; t < T_STEPS; t++) {
        const u64* __restrict__ hp = g_h2[t & 1];

        // early gi loads (this lane's own 2 gate columns, 3 gates)
        const float* gip = &g_gi[((size_t)t * BATCH + row) * HDIM3 + jcol];
        float2 gr = *(const float2*)gip;
        float2 gz = *(const float2*)(gip + HDIM);
        float2 gn = *(const float2*)(gip + 2 * HDIM);

        float acc[2][4];
#pragma unroll
        for (int nf = 0; nf < 2; nf++)
#pragma unroll
            for (int r = 0; r < 4; r++) acc[nf][r] = 0.f;

        // A-frag prefetch ring, depth PD=4.
        u64 pa[PD][4];
#pragma unroll
        for (int p = 0; p < PD; p++) {
            int ix = (p * 8 + tig) * BATCH + mbase + g;
            pa[p][0] = hp[ix];       pa[p][1] = hp[ix + 8];
            pa[p][2] = hp[ix + 512]; pa[p][3] = hp[ix + 520];
        }

#pragma unroll 4
        for (int kt = 0; kt < 32; kt++) {
            const int s = kt & (PD - 1);
            u64 d0 = pa[s][0], d1 = pa[s][1], d2 = pa[s][2], d3 = pa[s][3];
            if (kt + PD < 32) {
                int ix = ((kt + PD) * 8 + tig) * BATCH + mbase + g;
                pa[s][0] = hp[ix];       pa[s][1] = hp[ix + 8];
                pa[s][2] = hp[ix + 512]; pa[s][3] = hp[ix + 520];
            }
            u32 ah0 = (u32)d0, al0 = (u32)(d0 >> 32);
            u32 ah1 = (u32)d1, al1 = (u32)(d1 >> 32);
            u32 ah2 = (u32)d2, al2 = (u32)(d2 >> 32);
            u32 ah3 = (u32)d3, al3 = (u32)(d3 >> 32);
#pragma unroll
            for (int nf = 0; nf < 2; nf++) {
                u64 e0 = Bs[(kt * 8 + tig) * BS_STRIDE + nf * 8 + g];
                u64 e1 = Bs[(kt * 8 + tig + 4) * BS_STRIDE + nf * 8 + g];
                u32 bh0 = (u32)e0, bl0 = (u32)(e0 >> 32);
                u32 bh1 = (u32)e1, bl1 = (u32)(e1 >> 32);
                mma_bf16(acc[nf][0], acc[nf][1], acc[nf][2], acc[nf][3],
                         ah0, ah1, ah2, ah3, bh0, bh1);
                mma_bf16(acc[nf][0], acc[nf][1], acc[nf][2], acc[nf][3],
                         ah0, ah1, ah2, ah3, bl0, bl1);
                mma_bf16(acc[nf][0], acc[nf][1], acc[nf][2], acc[nf][3],
                         al0, al1, al2, al3, bh0, bh1);
            }
        }

        // Fragment exchange: partner lane = lane XOR 2 (tig0<->tig2, 1<->3).
        float sh0[4], sh1[4];
#pragma unroll
        for (int c = 0; c < 4; c++) {
            sh0[c] = __shfl_xor_sync(0xFFFFFFFFu, acc[0][c], 2);
            sh1[c] = __shfl_xor_sync(0xFFFFFFFFu, acc[1][c], 2);
        }

        // Gate inputs for this lane's (row, jc..jc+1):
        //  tig<2: row g    -> r = own c0/c1 (nf0), z = partner nf0 c0/c1,
        //                     n = own c0/c1 (nf1)
        //  tig>=2: row g+8 -> r = partner nf0 c2/c3, z = own nf0 c2/c3,
        //                     n = partner nf1 c2/c3
        float rin0, rin1, zin0, zin1, nin0, nin1;
        if ((tig & 2) == 0) {
            rin0 = acc[0][0]; rin1 = acc[0][1];
            zin0 = sh0[0];    zin1 = sh0[1];
            nin0 = acc[1][0]; nin1 = acc[1][1];
        } else {
            rin0 = sh0[2];    rin1 = sh0[3];
            zin0 = acc[0][2]; zin1 = acc[0][3];
            nin0 = sh1[2];    nin1 = sh1[3];
        }

        {
            float r0 = fast_sigmoid(gr.x + rin0);
            float r1 = fast_sigmoid(gr.y + rin1);
            float z0 = fast_sigmoid(gz.x + zin0);
            float z1 = fast_sigmoid(gz.y + zin1);
            float n0 = fast_tanh(gn.x + r0 * (nin0 + bn0));
            float n1 = fast_tanh(gn.y + r1 * (nin1 + bn1));
            hn0 = (1.0f - z0) * n0 + z0 * hn0;
            hn1 = (1.0f - z1) * n1 + z1 * hn1;
        }

        *(float2*)&out_ys[((size_t)t * BATCH + row) * HDIM + jcol] =
            make_float2(hn0, hn1);

        {
            u64* __restrict__ hq = g_h2[(t & 1) ^ 1];
            u32 hi, lo;
            split2_(hn0, hn1, hi, lo);
            hq[kp_out * BATCH + row] = (u64)hi | ((u64)lo << 32);
        }

        grid_barrier(SCAN_BLOCKS);
    }

    if (out_h) {
        *(float2*)&out_h[(size_t)row * HDIM + jcol] = make_float2(hn0, hn1);
    }
}

// ---------------------------------------------------------------------------
// kernel_launch: inputs per metadata order: x, h0, Wi, bi, Wh, bhn
// ---------------------------------------------------------------------------
extern "C" void kernel_launch(void* const* d_in, const int* in_sizes, int n_in,
                              void* d_out, int out_size)
{
    const float* x   = (const float*)d_in[0];   // [T, B, H]
    const float* h0  = (const float*)d_in[1];   // [B, H]
    const float* Wi  = (const float*)d_in[2];   // [H, 3H]
    const float* bi  = (const float*)d_in[3];   // [3H]
    const float* Wh  = (const float*)d_in[4];   // [H, 3H]
    const float* bhn = (const float*)d_in[5];   // [H]

    float* out = (float*)d_out;
    float* out_h;
    float* out_ys;
    const long long ys_elems = (long long)T_STEPS * BATCH * HDIM;
    if ((long long)out_size >= ys_elems + (long long)BATCH * HDIM) {
        out_h = out;                    // (h_final, ys) flattened in order
        out_ys = out + (size_t)BATCH * HDIM;
    } else {
        out_h = nullptr;                // ys only
        out_ys = out;
    }

    float* gi;
    cudaGetSymbolAddress((void**)&gi, g_gi);

    // 1) gi = x @ Wi + bi  (bf16 3-term compensated tensor-core GEMM)
    dim3 ggrid(HDIM3 / 128, (T_STEPS * BATCH) / 128);
    gemm_gi_tc_kernel<<<ggrid, 256>>>(x, Wi, bi, gi);

    // 2) persistent GRU scan (tensor-core per-step GEMV, shuffle epilogue)
    scan_kernel<<<SCAN_BLOCKS, SCAN_THREADS>>>(h0, Wh, bhn, out_h, out_ys);
}